// round 17
// baseline (speedup 1.0000x reference)
#include <cuda_runtime.h>
#include <cuda_fp16.h>

typedef unsigned int u32;

#define B_ 4
#define H_ 16
#define S_ 2048
#define D_ 64
#define NKT 16
#define THREADS 256
#define KQ_STR 36      // u32 per K smem row (144B stride; conflict-free ldmatrix)
#define VT_STR 68      // u32 per Vt smem row (272B stride; conflict-free ldmatrix)

__device__ u32   g_mbits[(size_t)B_ * S_ * (S_ / 32)];     // 2 MB mask bitfield
__device__ float g_inv[(size_t)B_ * H_ * S_];              // per-row 1/sum
__device__ u32   g_ebuf[(size_t)B_ * H_ * S_ * (S_ / 2)];  // 0.54 GB fp16x2 e-buffer
// pre-converted operands (hi plane only), tile-major
__device__ u32   g_khi[(size_t)B_ * H_ * S_ * 32];         // [bh][s][32 u32]
__device__ u32   g_vthi[(size_t)B_ * H_ * NKT * 4096];     // [bh][kt][64 d][64 kp]

#define KBUF   (128 * KQ_STR * 4)                          // 18432 B
#define VBUF   (64 * VT_STR * 4)                           // 17408 B
#define SMEM_F (2 * KBUF + 2 * VBUF)                       // 71680 B -> 2 CTAs/SM
#define VOFF   (2 * KBUF)

#define QSCALE 0.1803368801f                               // 0.125 * log2(e)

__device__ __forceinline__ void mma16816(float c[4], const u32 a[4], u32 b0, u32 b1) {
    asm volatile("mma.sync.aligned.m16n8k16.row.col.f32.f16.f16.f32 "
                 "{%0,%1,%2,%3}, {%4,%5,%6,%7}, {%8,%9}, {%0,%1,%2,%3};"
                 : "+f"(c[0]), "+f"(c[1]), "+f"(c[2]), "+f"(c[3])
                 : "r"(a[0]), "r"(a[1]), "r"(a[2]), "r"(a[3]), "r"(b0), "r"(b1));
}

__device__ __forceinline__ void ldm4(u32* r, u32 addr) {
    asm volatile("ldmatrix.sync.aligned.m8n8.x4.shared.b16 {%0,%1,%2,%3}, [%4];"
                 : "=r"(r[0]), "=r"(r[1]), "=r"(r[2]), "=r"(r[3]) : "r"(addr));
}

__device__ __forceinline__ u32 smem_u32(const void* p) {
    return (u32)__cvta_generic_to_shared(p);
}

__device__ __forceinline__ void cpa16(u32 dst, const void* src) {
    asm volatile("cp.async.cg.shared.global [%0], [%1], 16;" :: "r"(dst), "l"(src));
}
#define CP_COMMIT() asm volatile("cp.async.commit_group;" ::: "memory")
#define CP_WAIT1()  asm volatile("cp.async.wait_group 1;" ::: "memory")
#define CP_WAIT0()  asm volatile("cp.async.wait_group 0;" ::: "memory")

__device__ __forceinline__ void stcs64(u32* p, u32 a, u32 b) {
    asm volatile("st.global.cs.v2.u32 [%0], {%1,%2};" :: "l"(p), "r"(a), "r"(b) : "memory");
}

__device__ __forceinline__ u32 pack_h2(float x, float y) {
    __half2 H = __floats2half2_rn(x, y);
    return *reinterpret_cast<u32*>(&H);
}
__device__ __forceinline__ float2 unpack_h2(u32 v) {
    return __half22float2(*reinterpret_cast<__half2*>(&v));
}

__global__ void maskbits_kernel(const int* __restrict__ mask) {
    int w = blockIdx.x * blockDim.x + threadIdx.x;
    const int4* src = (const int4*)mask + (size_t)w * 8;
    u32 bits = 0;
    #pragma unroll
    for (int i = 0; i < 8; ++i) {
        int4 v = src[i];
        bits |= (v.x != 0 ? 1u : 0u) << (i * 4);
        bits |= (v.y != 0 ? 1u : 0u) << (i * 4 + 1);
        bits |= (v.z != 0 ? 1u : 0u) << (i * 4 + 2);
        bits |= (v.w != 0 ? 1u : 0u) << (i * 4 + 3);
    }
    g_mbits[w] = bits;
}

__global__ void conv_k(const float* __restrict__ K) {
    size_t idx = (size_t)blockIdx.x * blockDim.x + threadIdx.x;
    float4 v = ((const float4*)K)[idx];
    ((uint2*)g_khi)[idx] = make_uint2(pack_h2(v.x, v.y), pack_h2(v.z, v.w));
}

__global__ void conv_v(const float* __restrict__ V) {
    __shared__ u32 hi[64 * 64];
    const int kt = blockIdx.x, bh = blockIdx.y, tid = threadIdx.x;
    const float4* s4 = (const float4*)(V + ((size_t)bh * S_ + kt * 128) * D_);
    #pragma unroll
    for (int it = 0; it < 4; ++it) {
        int idx = it * THREADS + tid;
        int d4 = idx & 15, kp = idx >> 4;
        float4 a = s4[(2 * kp) * 16 + d4];
        float4 b = s4[(2 * kp + 1) * 16 + d4];
        float av[4] = {a.x, a.y, a.z, a.w};
        float bv[4] = {b.x, b.y, b.z, b.w};
        #pragma unroll
        for (int dd0 = 0; dd0 < 4; ++dd0) {
            int dd = (dd0 + d4) & 3;
            hi[(4 * d4 + dd) * 64 + kp] = pack_h2(av[dd], bv[dd]);
        }
    }
    __syncthreads();
    uint4* gh = (uint4*)(g_vthi + ((size_t)bh * NKT + kt) * 4096);
    #pragma unroll
    for (int it = 0; it < 4; ++it) {
        int idx = it * THREADS + tid;
        gh[idx] = ((uint4*)hi)[idx];
    }
}

__device__ __forceinline__ void stage_k_async(const u32* __restrict__ ghi, u32 smhi, int tid) {
    #pragma unroll
    for (int it = 0; it < 4; ++it) {
        int idx = it * THREADS + tid;
        int r = idx >> 3, c = idx & 7;
        cpa16(smhi + (u32)((r * KQ_STR + c * 4) * 4), ghi + (size_t)idx * 4);
    }
}
__device__ __forceinline__ void stage_v_async(const u32* __restrict__ ghi, u32 smhi, int tid) {
    #pragma unroll
    for (int it = 0; it < 4; ++it) {
        int idx = it * THREADS + tid;
        int r = idx >> 4, c = idx & 15;
        cpa16(smhi + (u32)((r * VT_STR + c * 4) * 4), ghi + (size_t)idx * 4);
    }
}

// ============ fused kernel: QK (fp16) -> e -> {e-buffer store, PV mma}, out UNNORMALIZED ============
__global__ __launch_bounds__(THREADS, 2)
void attn_fused(const float* __restrict__ Q, float* __restrict__ outp)
{
    extern __shared__ char sm[];

    const int tid = threadIdx.x, wid = tid >> 5, lane = tid & 31;
    const int g = lane >> 2, i = lane & 3;
    const int trow = lane & 7, tmat = lane >> 3;
    const int q0 = blockIdx.x * 128, bh = blockIdx.y, b = bh >> 4;
    const int qw = wid * 16;

    const u32* KbH = g_khi + (size_t)bh * S_ * 32;
    const u32* VbH = g_vthi + (size_t)bh * NKT * 4096;

    // Q fragments (hi only) from gmem, scale*log2e folded
    u32 qh[4][4];
    {
        const float* qa = Q + ((size_t)bh * S_ + q0 + qw + g) * D_;
        const float* qb = qa + 8 * D_;
        #pragma unroll
        for (int kc = 0; kc < 4; ++kc) {
            float2 a0 = *(const float2*)(qa + 16 * kc + 2 * i);
            float2 a1 = *(const float2*)(qa + 16 * kc + 8 + 2 * i);
            float2 b0 = *(const float2*)(qb + 16 * kc + 2 * i);
            float2 b1 = *(const float2*)(qb + 16 * kc + 8 + 2 * i);
            qh[kc][0] = pack_h2(a0.x * QSCALE, a0.y * QSCALE);
            qh[kc][1] = pack_h2(b0.x * QSCALE, b0.y * QSCALE);
            qh[kc][2] = pack_h2(a1.x * QSCALE, a1.y * QSCALE);
            qh[kc][3] = pack_h2(b1.x * QSCALE, b1.y * QSCALE);
        }
    }

    const u32* mra = g_mbits + (size_t)(b * S_ + q0 + qw + g) * (S_ / 32);
    const u32* mrb = mra + 8 * (S_ / 32);
    u32* ebA = g_ebuf + (size_t)(bh * S_ + q0 + qw + g) * (S_ / 2);
    u32* ebB = ebA + 8 * (S_ / 2);

    float o[8][4];
    #pragma unroll
    for (int d = 0; d < 8; ++d) o[d][0] = o[d][1] = o[d][2] = o[d][3] = 0.f;

    const u32 smbase = smem_u32(sm);
    stage_k_async(KbH, smbase, tid);
    stage_v_async(VbH, smbase + VOFF, tid);
    CP_COMMIT();

    for (int kt = 0; kt < NKT; ++kt) {
        if (kt + 1 < NKT) {
            stage_k_async(KbH + (size_t)(kt + 1) * 128 * 32,
                          smbase + ((kt + 1) & 1) * KBUF, tid);
            stage_v_async(VbH + (size_t)(kt + 1) * 4096,
                          smbase + VOFF + ((kt + 1) & 1) * VBUF, tid);
            CP_COMMIT();
            CP_WAIT1();
        } else {
            CP_WAIT0();
        }
        __syncthreads();

        const u32 khi_u  = smbase + (kt & 1) * KBUF;
        const u32 vthi_u = smbase + VOFF + (kt & 1) * VBUF;

        const uint4 wa4 = *(const uint4*)(mra + kt * 4);
        const uint4 wb4 = *(const uint4*)(mrb + kt * 4);
        const u32 waw[4] = {wa4.x, wa4.y, wa4.z, wa4.w};
        const u32 wbw[4] = {wb4.x, wb4.y, wb4.z, wb4.w};

        #pragma unroll
        for (int sub = 0; sub < 2; ++sub) {
            #pragma unroll
            for (int jq = 0; jq < 2; ++jq) {
                float c[4][4];
                #pragma unroll
                for (int j = 0; j < 4; ++j)
                    c[j][0] = c[j][1] = c[j][2] = c[j][3] = 0.f;

                // ---- QK MMAs (fp16 single product) ----
                #pragma unroll
                for (int j4 = 0; j4 < 4; ++j4) {
                    int nrow = sub * 64 + jq * 32 + j4 * 8 + trow;
                    u32 rb = (u32)((nrow * KQ_STR + tmat * 4) * 4);
                    u32 bhv[8];
                    ldm4(&bhv[0], khi_u + rb);
                    ldm4(&bhv[4], khi_u + rb + 64);
                    #pragma unroll
                    for (int kc = 0; kc < 4; ++kc)
                        mma16816(c[j4], qh[kc], bhv[2 * kc], bhv[2 * kc + 1]);
                }

                // ---- mask + exp2 (no row sums here anymore) ----
                const u32 was = waw[sub * 2 + jq] >> (2 * i);
                const u32 wbs = wbw[sub * 2 + jq] >> (2 * i);
                #pragma unroll
                for (int j4 = 0; j4 < 4; ++j4) {
                    u32 ba = was >> (j4 * 8), bb = wbs >> (j4 * 8);
                    c[j4][0] = (ba & 1u) ? exp2f(c[j4][0]) : 0.f;
                    c[j4][1] = (ba & 2u) ? exp2f(c[j4][1]) : 0.f;
                    c[j4][2] = (bb & 1u) ? exp2f(c[j4][2]) : 0.f;
                    c[j4][3] = (bb & 2u) ? exp2f(c[j4][3]) : 0.f;
                }

                // ---- pack e fragments; store to e-buffer (uint2); PV mma from regs ----
                const int grp = kt * 64 + sub * 32 + jq * 16;
                u32 aa[2][4];
                #pragma unroll
                for (int kc2 = 0; kc2 < 2; ++kc2) {
                    aa[kc2][0] = pack_h2(c[2 * kc2][0],     c[2 * kc2][1]);
                    aa[kc2][1] = pack_h2(c[2 * kc2][2],     c[2 * kc2][3]);
                    aa[kc2][2] = pack_h2(c[2 * kc2 + 1][0], c[2 * kc2 + 1][1]);
                    aa[kc2][3] = pack_h2(c[2 * kc2 + 1][2], c[2 * kc2 + 1][3]);
                    stcs64(&ebA[grp + kc2 * 8 + 2 * i], aa[kc2][0], aa[kc2][2]);
                    stcs64(&ebB[grp + kc2 * 8 + 2 * i], aa[kc2][1], aa[kc2][3]);
                }

                #pragma unroll
                for (int dblk = 0; dblk < 8; ++dblk) {
                    u32 rb = (u32)(((dblk * 8 + trow) * VT_STR
                                    + sub * 32 + jq * 16 + tmat * 4) * 4);
                    u32 vh[4];
                    ldm4(vh, vthi_u + rb);
                    #pragma unroll
                    for (int kc2 = 0; kc2 < 2; ++kc2)
                        mma16816(o[dblk], aa[kc2], vh[2 * kc2], vh[2 * kc2 + 1]);
                }
            }
        }
        __syncthreads();
    }

    // ---- epilogue: write UNNORMALIZED out (onorm scales it after norm computes inv) ----
    if (outp) {
        float* orowA = outp + ((size_t)bh * S_ + q0 + qw + g) * D_ + 2 * i;
        float* orowB = orowA + 8 * D_;
        #pragma unroll
        for (int dblk = 0; dblk < 8; ++dblk) {
            *(float2*)&orowA[dblk * 8] = make_float2(o[dblk][0], o[dblk][1]);
            *(float2*)&orowB[dblk * 8] = make_float2(o[dblk][2], o[dblk][3]);
        }
    }
}

// ============ norm pass: one CTA per row — row sum -> inv -> normalized attn + g_inv ============
__global__ __launch_bounds__(THREADS, 4)
void norm_kernel(float* __restrict__ attn) {
    __shared__ float red[8];
    __shared__ float sinv;
    const size_t row = blockIdx.x;
    const int v = threadIdx.x;                  // uint4 index within row (0..255)
    const int lane = v & 31, wrp = v >> 5;

    uint4 w = __ldcs((const uint4*)g_ebuf + row * 256 + v);
    float2 fx = unpack_h2(w.x), fy = unpack_h2(w.y);
    float2 fz = unpack_h2(w.z), fw = unpack_h2(w.w);

    float s = ((fx.x + fx.y) + (fy.x + fy.y)) + ((fz.x + fz.y) + (fw.x + fw.y));
    #pragma unroll
    for (int off = 16; off; off >>= 1) s += __shfl_xor_sync(0xffffffffu, s, off);
    if (lane == 0) red[wrp] = s;
    __syncthreads();
    if (v == 0) {
        float t = red[0] + red[1] + red[2] + red[3] + red[4] + red[5] + red[6] + red[7];
        float inv = (t > 0.f) ? (1.0f / t) : 0.f;
        g_inv[row] = inv;
        sinv = inv;
    }
    __syncthreads();
    const float inv = sinv;

    if (attn) {
        int col1 = 2 * ((v >> 2) * 16 + ((v >> 1) & 1) * 8 + (v & 1) * 2);
        float* arow = attn + row * S_;
        __stcs((float4*)(arow + col1),
               make_float4(fx.x * inv, fx.y * inv, fz.x * inv, fz.y * inv));
        __stcs((float4*)(arow + col1 + 8),
               make_float4(fy.x * inv, fy.y * inv, fw.x * inv, fw.y * inv));
    }
}

// ============ out normalization: out[row][:] *= g_inv[row] ============
__global__ void onorm_kernel(float* __restrict__ outp) {
    size_t t = (size_t)blockIdx.x * blockDim.x + threadIdx.x;   // float4 index
    float inv = __ldg(&g_inv[t >> 4]);                          // 16 float4 per row
    float4 v = ((const float4*)outp)[t];
    v.x *= inv; v.y *= inv; v.z *= inv; v.w *= inv;
    ((float4*)outp)[t] = v;
}

extern "C" void kernel_launch(void* const* d_in, const int* in_sizes, int n_in,
                              void* d_out, int out_size)
{
    const float* Q    = (const float*)d_in[0];
    const float* K    = (const float*)d_in[1];
    const float* V    = (const float*)d_in[2];
    const int*   mask = (const int*)d_in[3];

    const size_t OUT_E  = (size_t)B_ * H_ * S_ * D_;
    const size_t ATTN_E = (size_t)B_ * H_ * S_ * S_;
    float* o = nullptr; float* a = nullptr;
    if ((size_t)out_size >= OUT_E + ATTN_E) { o = (float*)d_out; a = (float*)d_out + OUT_E; }
    else if ((size_t)out_size == ATTN_E)    { a = (float*)d_out; }
    else                                    { o = (float*)d_out; }

    maskbits_kernel<<<(B_ * S_ * (S_ / 32)) / 256, 256>>>(mask);
    conv_k<<<(B_ * H_ * S_ * (D_ / 4)) / 256, 256>>>(K);
    conv_v<<<dim3(NKT, B_ * H_), 256>>>(V);

    cudaFuncSetAttribute(attn_fused, cudaFuncAttributeMaxDynamicSharedMemorySize, SMEM_F);

    dim3 grid(S_ / 128, B_ * H_);
    attn_fused<<<grid, THREADS, SMEM_F>>>(Q, o);

    // norm always runs: computes g_inv (and attn if requested)
    norm_kernel<<<B_ * H_ * S_, THREADS>>>(a);

    if (o) {
        onorm_kernel<<<(unsigned)(OUT_E / 4 / 256), 256>>>(o);
    }
}